// round 15
// baseline (speedup 1.0000x reference)
#include <cuda_runtime.h>
#include <cuda_fp16.h>
#include <math.h>

#define NN   100000
#define EE   1600000
#define HID  64
#define NL   5
#define NB   512
#define SCAN_T 512
#define SCAN_BLOCKS 196          /* ceil(100000/512) */

/* ------------------------------------------------------------------ */
/* device scratch (h lives only as fp16)                               */
/* ------------------------------------------------------------------ */
__device__ __half g_h16[NN * HID];            /* node features (fp16) */
__device__ __half g_u[NN * HID];
__device__ float  g_t[NN * HID];
__device__ __half g_e[(size_t)EE * HID];      /* 204.8 MB, CSR order  */
__device__ __half g_wh[NL * 4 * HID * HID];   /* fp16 MLP weights     */
__device__ int    g_deg[NN];
__device__ int    g_cur[NN];
__device__ int    g_incl[SCAN_BLOCKS * SCAN_T];
__device__ int    g_bsum[SCAN_BLOCKS];
__device__ int    g_off[NN + 1];
__device__ int    g_csr_src[EE];
__device__ int    g_csr_eid[EE];
__device__ double g_colsum[HID];
__device__ double g_colsq[HID];
__device__ float  g_scale[HID];
__device__ float  g_shift[HID];
__device__ float  g_gcnt[NB];

/* ------------------------------------------------------------------ */
/* packed f32x2 helpers                                                */
/* ------------------------------------------------------------------ */
typedef unsigned long long pf2;

__device__ __forceinline__ pf2 pk2(float lo, float hi) {
    pf2 d;
    asm("mov.b64 %0, {%1, %2};" : "=l"(d)
        : "r"(__float_as_uint(lo)), "r"(__float_as_uint(hi)));
    return d;
}
__device__ __forceinline__ void upk2(pf2 d, float &lo, float &hi) {
    unsigned a, b;
    asm("mov.b64 {%0, %1}, %2;" : "=r"(a), "=r"(b) : "l"(d));
    lo = __uint_as_float(a); hi = __uint_as_float(b);
}
__device__ __forceinline__ pf2 fma2(pf2 a, pf2 b, pf2 c) {
    pf2 d;
    asm("fma.rn.f32x2 %0, %1, %2, %3;" : "=l"(d) : "l"(a), "l"(b), "l"(c));
    return d;
}
__device__ __forceinline__ unsigned sptr(const void *p) {
    return (unsigned)__cvta_generic_to_shared(p);
}
/* streaming (evict-first) half2 load via b32 */
__device__ __forceinline__ __half2 ldcs_h2(const __half *p) {
    unsigned u = __ldcs((const unsigned *)p);
    return *(__half2 *)&u;
}

/* ------------------------------------------------------------------ */
/* CSR build                                                           */
/* ------------------------------------------------------------------ */
__global__ void k_zero2() {
    int i = blockIdx.x * blockDim.x + threadIdx.x;
    if (i < NN) { g_deg[i] = 0; g_cur[i] = 0; }
    if (i < HID) { g_colsum[i] = 0.0; g_colsq[i] = 0.0; }
}

__global__ void k_hist(const int *__restrict__ ei) {
    int i = blockIdx.x * blockDim.x + threadIdx.x;
    if (i < EE) atomicAdd(&g_deg[__ldcs(ei + EE + i)], 1);
}

__global__ void k_scan_partial() {
    __shared__ int s[SCAN_T];
    int tid = threadIdx.x;
    int idx = blockIdx.x * SCAN_T + tid;
    int v = (idx < NN) ? g_deg[idx] : 0;
    s[tid] = v;
    __syncthreads();
#pragma unroll
    for (int d = 1; d < SCAN_T; d <<= 1) {
        int t = (tid >= d) ? s[tid - d] : 0;
        __syncthreads();
        s[tid] += t;
        __syncthreads();
    }
    g_incl[idx] = s[tid];
    if (tid == SCAN_T - 1) g_bsum[blockIdx.x] = s[tid];
}

__global__ void k_scan_bsum() {
    __shared__ int s[256];
    int tid = threadIdx.x;
    int v = (tid < SCAN_BLOCKS) ? g_bsum[tid] : 0;
    s[tid] = v;
    __syncthreads();
#pragma unroll
    for (int d = 1; d < 256; d <<= 1) {
        int t = (tid >= d) ? s[tid - d] : 0;
        __syncthreads();
        s[tid] += t;
        __syncthreads();
    }
    if (tid < SCAN_BLOCKS) g_bsum[tid] = s[tid] - v;   /* exclusive */
}

__global__ void k_scan_add() {
    int i = blockIdx.x * blockDim.x + threadIdx.x;
    if (i <= NN)
        g_off[i] = (i == 0) ? 0 : g_incl[i - 1] + g_bsum[(i - 1) >> 9];
}

__global__ void k_scatter(const int *__restrict__ ei) {
    int i = blockIdx.x * blockDim.x + threadIdx.x;
    if (i < EE) {
        int d = __ldcs(ei + EE + i);
        int p = g_off[d] + atomicAdd(&g_cur[d], 1);
        g_csr_src[p] = __ldcs(ei + i);
        g_csr_eid[p] = i;
    }
}

/* ------------------------------------------------------------------ */
/* MLP weight fp32 -> fp16                                             */
/* ------------------------------------------------------------------ */
__global__ void k_wconv(const float *__restrict__ W) {
    int i = blockIdx.x * blockDim.x + threadIdx.x;
    if (i < NL * 4 * HID * HID) g_wh[i] = __float2half(W[i]);
}

/* ------------------------------------------------------------------ */
/* edge projection (GEMM tile): e[slot] = edge_attr[eid]@W + b (fp16)  */
/* ------------------------------------------------------------------ */
__global__ void __launch_bounds__(256, 4)
k_edgeproj(const float *__restrict__ ea,
           const float *__restrict__ W,
           const float *__restrict__ b) {
    __shared__ float sA[128 * 16];
    __shared__ float sW[16 * 64];
    __shared__ float sB[64];
    int tid = threadIdx.x;
    int m0 = blockIdx.x * 128;

    ((float4 *)sW)[tid] = ((const float4 *)W)[tid];
    if (tid < 16) ((float4 *)sB)[tid] = ((const float4 *)b)[tid];

    for (int i = tid; i < 512; i += 256) {
        int r = i >> 2, q = i & 3;
        float4 v = make_float4(0.f, 0.f, 0.f, 0.f);
        int slot = m0 + r;
        if (slot < EE) {
            int eid = __ldcs(g_csr_eid + slot);
            v = __ldcs((const float4 *)(ea + (size_t)eid * 16 + q * 4));
        }
        *(float4 *)(sA + r * 16 + q * 4) = v;
    }
    __syncthreads();

    int tx = tid & 15, ty = tid >> 4;
    int r0 = ty * 8, c0 = tx * 4;

    pf2 acc[8][2];
#pragma unroll
    for (int i = 0; i < 8; i++) { acc[i][0] = 0ull; acc[i][1] = 0ull; }

#pragma unroll
    for (int k = 0; k < 16; k++) {
        float4 w = *(const float4 *)(sW + k * 64 + c0);
        pf2 w01 = pk2(w.x, w.y), w23 = pk2(w.z, w.w);
#pragma unroll
        for (int i = 0; i < 8; i++) {
            float av = sA[(r0 + i) * 16 + k];
            pf2 ad = pk2(av, av);
            acc[i][0] = fma2(ad, w01, acc[i][0]);
            acc[i][1] = fma2(ad, w23, acc[i][1]);
        }
    }

    float bx = sB[c0], by = sB[c0 + 1], bz = sB[c0 + 2], bw = sB[c0 + 3];
#pragma unroll
    for (int i = 0; i < 8; i++) {
        int slot = m0 + r0 + i;
        if (slot < EE) {
            float x0, x1, x2, x3;
            upk2(acc[i][0], x0, x1);
            upk2(acc[i][1], x2, x3);
            union { uint2 u2; __half2 h2[2]; } pk;
            pk.h2[0] = __floats2half2_rn(x0 + bx, x1 + by);
            pk.h2[1] = __floats2half2_rn(x2 + bz, x3 + bw);
            __stcs((uint2 *)(g_e + (size_t)slot * 64 + c0), pk.u2);
        }
    }
}

/* ------------------------------------------------------------------ */
/* node projection (fp32 FFMA2 tile, runs once); writes h16 only       */
/* ------------------------------------------------------------------ */
#define NP_SMEM ((128 * 64 + 64 * 64 + 64) * 4)

__global__ void __launch_bounds__(256, 2)
k_nodeproj(const float *__restrict__ in,
           const float *__restrict__ W, const float *__restrict__ b) {
    extern __shared__ float smf[];
    float *sA = smf;
    float *sW = sA + 128 * 64;
    float *sB = sW + 64 * 64;
    int tid = threadIdx.x;
    int m0 = blockIdx.x * 128;

    for (int i = tid; i < 2048; i += 256) {
        int r = i >> 4, q = i & 15;
        float4 v = make_float4(0.f, 0.f, 0.f, 0.f);
        if (m0 + r < NN)
            v = *(const float4 *)(in + (size_t)(m0 + r) * 64 + q * 4);
        *(float4 *)(sA + r * 64 + q * 4) = v;
    }
    for (int i = tid; i < 1024; i += 256)
        ((float4 *)sW)[i] = ((const float4 *)W)[i];
    if (tid < 16) ((float4 *)sB)[tid] = ((const float4 *)b)[tid];
    __syncthreads();

    int tx = tid & 15, ty = tid >> 4;
    int r0 = ty * 8, c0 = tx * 4;

    pf2 acc[8][2];
#pragma unroll
    for (int i = 0; i < 8; i++) { acc[i][0] = 0ull; acc[i][1] = 0ull; }

#pragma unroll
    for (int kk = 0; kk < 64; kk += 4) {
        float4 a[8];
#pragma unroll
        for (int i = 0; i < 8; i++)
            a[i] = *(const float4 *)(sA + (r0 + i) * 64 + kk);
#pragma unroll
        for (int k4 = 0; k4 < 4; k4++) {
            float4 w = *(const float4 *)(sW + (kk + k4) * 64 + c0);
            pf2 w01 = pk2(w.x, w.y), w23 = pk2(w.z, w.w);
#pragma unroll
            for (int i = 0; i < 8; i++) {
                float av = (k4 == 0) ? a[i].x : (k4 == 1) ? a[i].y
                         : (k4 == 2) ? a[i].z : a[i].w;
                pf2 ad = pk2(av, av);
                acc[i][0] = fma2(ad, w01, acc[i][0]);
                acc[i][1] = fma2(ad, w23, acc[i][1]);
            }
        }
    }

    float bx = sB[c0], by = sB[c0 + 1], bz = sB[c0 + 2], bw = sB[c0 + 3];
#pragma unroll
    for (int i = 0; i < 8; i++) {
        if (m0 + r0 + i < NN) {
            float x0, x1, x2, x3;
            upk2(acc[i][0], x0, x1);
            upk2(acc[i][1], x2, x3);
            x0 += bx; x1 += by; x2 += bz; x3 += bw;
            union { uint2 u2; __half2 h2[2]; } pk;
            pk.h2[0] = __floats2half2_rn(x0, x1);
            pk.h2[1] = __floats2half2_rn(x2, x3);
            *(uint2 *)(g_h16 + (size_t)(m0 + r0 + i) * 64 + c0) = pk.u2;
        }
    }
}

/* ------------------------------------------------------------------ */
/* aggregation: u[v] = (1+eps)*h16[v] + sum relu(h16[s]+e)             */
/* ------------------------------------------------------------------ */
__global__ void k_aggr(const float *__restrict__ eps_arr, int l) {
    int v = blockIdx.x * 8 + (threadIdx.x >> 5);
    if (v >= NN) return;
    int lane = threadIdx.x & 31;
    int f0 = lane * 2;
    float ep = 1.0f + __ldg(&eps_arr[l]);

    float2 hv = __half22float2(*(const __half2 *)(g_h16 + (size_t)v * 64 + f0));
    float ax = ep * hv.x, ay = ep * hv.y;

    int beg = g_off[v], end = g_off[v + 1];
    const __half2 z2 = __float2half2_rn(0.f);
    int p = beg;
    for (; p + 2 <= end; p += 2) {
        int s0 = __ldcs(g_csr_src + p), s1 = __ldcs(g_csr_src + p + 1);
        __half2 h0 = *(const __half2 *)(g_h16 + (size_t)s0 * 64 + f0);
        __half2 h1 = *(const __half2 *)(g_h16 + (size_t)s1 * 64 + f0);
        __half2 e0 = ldcs_h2(g_e + (size_t)p * 64 + f0);
        __half2 e1 = ldcs_h2(g_e + (size_t)(p + 1) * 64 + f0);
        float2 m0 = __half22float2(__hmax2(__hadd2(h0, e0), z2));
        float2 m1 = __half22float2(__hmax2(__hadd2(h1, e1), z2));
        ax += m0.x + m1.x;
        ay += m0.y + m1.y;
    }
    if (p < end) {
        int s0 = __ldcs(g_csr_src + p);
        __half2 h0 = *(const __half2 *)(g_h16 + (size_t)s0 * 64 + f0);
        __half2 e0 = ldcs_h2(g_e + (size_t)p * 64 + f0);
        float2 m0 = __half22float2(__hmax2(__hadd2(h0, e0), z2));
        ax += m0.x;
        ay += m0.y;
    }
    *(__half2 *)(g_u + (size_t)v * 64 + f0) = __floats2half2_rn(ax, ay);
}

/* ------------------------------------------------------------------ */
/* MLP via HMMA: 4 x (64x64 linear [+relu]), fp16 in, fp32 out (t)     */
/* t stored with default policy — stays L2-resident for k_apply        */
/* ------------------------------------------------------------------ */
#define MLP_SMEM (128*72*2*2 + 64*72*2 + 64*4 + 64*4 + 64*4)

__global__ void __launch_bounds__(256, 3)
k_mlp_mma(const __half *__restrict__ in, float *__restrict__ out,
          const __half *__restrict__ Wh, const float *__restrict__ bb, int M) {
    extern __shared__ char smc[];
    __half *sA0  = (__half *)smc;          /* 128 x 72 */
    __half *sA1  = sA0 + 128 * 72;         /* 128 x 72 */
    __half *sW   = sA1 + 128 * 72;         /* 64 x 72  */
    float  *sBias = (float *)(sW + 64 * 72);
    float  *sPs  = sBias + 64;
    float  *sPq  = sPs + 64;

    int tid = threadIdx.x;
    int lane = tid & 31, wid = tid >> 5;
    int m0 = wid * 16;
    int mg0 = blockIdx.x * 128;

    if (tid < 64) { sPs[tid] = 0.f; sPq[tid] = 0.f; }

#pragma unroll
    for (int j = 0; j < 4; j++) {
        int idx = tid + 256 * j;
        int r = idx >> 3, q = idx & 7;
        uint4 v = make_uint4(0, 0, 0, 0);
        if (mg0 + r < M)
            v = *(const uint4 *)(in + (size_t)(mg0 + r) * 64 + q * 8);
        *(uint4 *)(sA0 + r * 72 + q * 8) = v;
    }

    int gid = lane >> 2, tig = lane & 3;

    for (int s = 0; s < 4; s++) {
        __syncthreads();
        const __half *Ws = Wh + s * 4096;
        {
            int idx = tid * 2;
            int r = idx >> 3, q = idx & 7;
            *(uint4 *)(sW + r * 72 + q * 8) = *(const uint4 *)(Ws + r * 64 + q * 8);
            idx++;
            r = idx >> 3; q = idx & 7;
            *(uint4 *)(sW + r * 72 + q * 8) = *(const uint4 *)(Ws + r * 64 + q * 8);
        }
        if (tid < 64) sBias[tid] = bb[s * 64 + tid];
        __syncthreads();

        __half *sIn  = (s & 1) ? sA1 : sA0;
        __half *sOut = (s & 1) ? sA0 : sA1;

        float acc[8][4];
#pragma unroll
        for (int nt = 0; nt < 8; nt++)
#pragma unroll
            for (int i = 0; i < 4; i++) acc[nt][i] = 0.f;

#pragma unroll
        for (int kc = 0; kc < 4; kc++) {
            int k = kc * 16;
            unsigned a0, a1, a2, a3;
            unsigned aaddr = sptr(sIn + (m0 + (lane & 15)) * 72 + k + ((lane >> 4) << 3));
            asm volatile("ldmatrix.sync.aligned.m8n8.x4.shared.b16 {%0,%1,%2,%3}, [%4];"
                         : "=r"(a0), "=r"(a1), "=r"(a2), "=r"(a3) : "r"(aaddr));
#pragma unroll
            for (int nt = 0; nt < 8; nt++) {
                unsigned b0, b1;
                unsigned baddr = sptr(sW + (k + (lane & 15)) * 72 + nt * 8);
                asm volatile("ldmatrix.sync.aligned.m8n8.x2.trans.shared.b16 {%0,%1}, [%2];"
                             : "=r"(b0), "=r"(b1) : "r"(baddr));
                asm volatile(
                    "mma.sync.aligned.m16n8k16.row.col.f32.f16.f16.f32 "
                    "{%0,%1,%2,%3}, {%4,%5,%6,%7}, {%8,%9}, {%0,%1,%2,%3};"
                    : "+f"(acc[nt][0]), "+f"(acc[nt][1]),
                      "+f"(acc[nt][2]), "+f"(acc[nt][3])
                    : "r"(a0), "r"(a1), "r"(a2), "r"(a3), "r"(b0), "r"(b1));
            }
        }

        bool last = (s == 3);
#pragma unroll
        for (int nt = 0; nt < 8; nt++) {
            int col = nt * 8 + 2 * tig;
            float b0f = sBias[col], b1f = sBias[col + 1];
            float v0 = acc[nt][0] + b0f;
            float v1 = acc[nt][1] + b1f;
            float v2 = acc[nt][2] + b0f;
            float v3 = acc[nt][3] + b1f;
            if (!last) {
                v0 = fmaxf(v0, 0.f); v1 = fmaxf(v1, 0.f);
                v2 = fmaxf(v2, 0.f); v3 = fmaxf(v3, 0.f);
                *(__half2 *)(sOut + (m0 + gid) * 72 + col)     = __floats2half2_rn(v0, v1);
                *(__half2 *)(sOut + (m0 + gid + 8) * 72 + col) = __floats2half2_rn(v2, v3);
            } else {
                int r0g = mg0 + m0 + gid, r1g = r0g + 8;
                bool ok0 = r0g < M, ok1 = r1g < M;
                if (ok0) *(float2 *)(out + (size_t)r0g * 64 + col) = make_float2(v0, v1);
                if (ok1) *(float2 *)(out + (size_t)r1g * 64 + col) = make_float2(v2, v3);
                if (!ok0) { v0 = 0.f; v1 = 0.f; }
                if (!ok1) { v2 = 0.f; v3 = 0.f; }
                float s0 = v0 + v2, s1 = v1 + v3;
                float q0 = v0 * v0 + v2 * v2, q1 = v1 * v1 + v3 * v3;
#pragma unroll
                for (int o = 4; o < 32; o <<= 1) {
                    s0 += __shfl_xor_sync(0xffffffffu, s0, o);
                    s1 += __shfl_xor_sync(0xffffffffu, s1, o);
                    q0 += __shfl_xor_sync(0xffffffffu, q0, o);
                    q1 += __shfl_xor_sync(0xffffffffu, q1, o);
                }
                if (lane < 4) {
                    atomicAdd(&sPs[col], s0);
                    atomicAdd(&sPs[col + 1], s1);
                    atomicAdd(&sPq[col], q0);
                    atomicAdd(&sPq[col + 1], q1);
                }
            }
        }
    }

    __syncthreads();
    if (tid < 64) {
        atomicAdd(&g_colsum[tid], (double)sPs[tid]);
        atomicAdd(&g_colsq[tid], (double)sPq[tid]);
    }
}

/* ------------------------------------------------------------------ */
/* BN finalize (single block; re-zeroes accumulators)                  */
/* ------------------------------------------------------------------ */
__global__ void k_bn_finalize(const float *__restrict__ gamma,
                              const float *__restrict__ beta, int l) {
    int c = threadIdx.x;
    if (c < HID) {
        double mu  = g_colsum[c] / (double)NN;
        double var = g_colsq[c] / (double)NN - mu * mu;
        float s = (float)(1.0 / sqrt(var + 1e-5)) * gamma[l * HID + c];
        g_scale[c] = s;
        g_shift[c] = beta[l * HID + c] - (float)mu * s;
        g_colsum[c] = 0.0;
        g_colsq[c]  = 0.0;
    }
}

/* ------------------------------------------------------------------ */
/* BN apply + relu + residual; t read plain (L2 hit expected)          */
/* ------------------------------------------------------------------ */
__global__ void k_apply() {
    __shared__ float ss[64], sh[64];
    int tid = threadIdx.x;
    if (tid < 64) { ss[tid] = g_scale[tid]; sh[tid] = g_shift[tid]; }
    __syncthreads();
    int i = blockIdx.x * blockDim.x + tid;
    if (i < NN * 16) {
        int c = (i & 15) * 4;
        float4 t = ((const float4 *)g_t)[i];
        union { uint2 u2; __half2 h2[2]; } H;
        H.u2 = ((const uint2 *)g_h16)[i];
        float2 h01 = __half22float2(H.h2[0]);
        float2 h23 = __half22float2(H.h2[1]);
        float r0 = fmaxf(fmaf(t.x, ss[c + 0], sh[c + 0]), 0.f) + h01.x;
        float r1 = fmaxf(fmaf(t.y, ss[c + 1], sh[c + 1]), 0.f) + h01.y;
        float r2 = fmaxf(fmaf(t.z, ss[c + 2], sh[c + 2]), 0.f) + h23.x;
        float r3 = fmaxf(fmaf(t.w, ss[c + 3], sh[c + 3]), 0.f) + h23.y;
        union { uint2 u2; __half2 h2[2]; } pk;
        pk.h2[0] = __floats2half2_rn(r0, r1);
        pk.h2[1] = __floats2half2_rn(r2, r3);
        ((uint2 *)g_h16)[i] = pk.u2;
    }
}

/* ------------------------------------------------------------------ */
/* global mean pool (reads h16)                                        */
/* ------------------------------------------------------------------ */
__global__ void k_pool_zero(float *__restrict__ out) {
    int i = blockIdx.x * blockDim.x + threadIdx.x;
    if (i < NB * HID) out[i] = 0.f;
    if (i < NB) g_gcnt[i] = 0.f;
}

__global__ void k_pool_sum(const int *__restrict__ batch,
                           float *__restrict__ out) {
    int v = blockIdx.x * 8 + (threadIdx.x >> 5);
    if (v >= NN) return;
    int lane = threadIdx.x & 31;
    int f0 = lane * 2;
    int b = batch[v];
    float2 hv = __half22float2(*(const __half2 *)(g_h16 + (size_t)v * 64 + f0));
    atomicAdd(&out[b * 64 + f0], hv.x);
    atomicAdd(&out[b * 64 + f0 + 1], hv.y);
    if (lane == 0) atomicAdd(&g_gcnt[b], 1.0f);
}

__global__ void k_pool_div(float *__restrict__ out) {
    int i = blockIdx.x * blockDim.x + threadIdx.x;
    if (i < NB * HID) out[i] /= fmaxf(g_gcnt[i >> 6], 1.0f);
}

/* ------------------------------------------------------------------ */
/* launch                                                              */
/* ------------------------------------------------------------------ */
extern "C" void kernel_launch(void *const *d_in, const int *in_sizes, int n_in,
                              void *d_out, int out_size) {
    const float *x         = (const float *)d_in[0];
    const float *edge_attr = (const float *)d_in[1];
    const float *node_W    = (const float *)d_in[2];
    const float *node_b    = (const float *)d_in[3];
    const float *edge_W    = (const float *)d_in[4];
    const float *edge_b    = (const float *)d_in[5];
    const float *eps_arr   = (const float *)d_in[6];
    const float *mlp_W     = (const float *)d_in[7];
    const float *mlp_b     = (const float *)d_in[8];
    const float *bn_gamma  = (const float *)d_in[9];
    const float *bn_beta   = (const float *)d_in[10];
    const int   *edge_index = (const int *)d_in[11];
    const int   *batch      = (const int *)d_in[12];
    float *out = (float *)d_out;

    cudaFuncSetAttribute(k_nodeproj,
                         cudaFuncAttributeMaxDynamicSharedMemorySize, NP_SMEM);
    cudaFuncSetAttribute(k_mlp_mma,
                         cudaFuncAttributeMaxDynamicSharedMemorySize, MLP_SMEM);

    float *pt;
    __half *pu, *pwh;
    cudaGetSymbolAddress((void **)&pt, g_t);
    cudaGetSymbolAddress((void **)&pu, g_u);
    cudaGetSymbolAddress((void **)&pwh, g_wh);

    const int LIN_BLOCKS = (NN + 127) / 128;       /* 782   */
    const int EP_BLOCKS  = (EE + 127) / 128;       /* 12500 */
    const int WARP8      = (NN + 7) / 8;           /* 12500 */

    /* ---- preprocessing ---- */
    k_zero2<<<(NN + 255) / 256, 256>>>();
    k_hist<<<(EE + 255) / 256, 256>>>(edge_index);
    k_scan_partial<<<SCAN_BLOCKS, SCAN_T>>>();
    k_scan_bsum<<<1, 256>>>();
    k_scan_add<<<(NN + 256) / 256, 256>>>();
    k_scatter<<<(EE + 255) / 256, 256>>>(edge_index);
    k_edgeproj<<<EP_BLOCKS, 256>>>(edge_attr, edge_W, edge_b);
    k_wconv<<<(NL * 4 * HID * HID + 255) / 256, 256>>>(mlp_W);

    /* node projection */
    k_nodeproj<<<LIN_BLOCKS, 256, NP_SMEM>>>(x, node_W, node_b);

    /* ---- layers ---- */
    for (int l = 0; l < NL; l++) {
        k_aggr<<<WARP8, 256>>>(eps_arr, l);
        k_mlp_mma<<<LIN_BLOCKS, 256, MLP_SMEM>>>(
            pu, pt, pwh + (size_t)l * 4 * 4096, mlp_b + (size_t)l * 4 * 64, NN);
        k_bn_finalize<<<1, 64>>>(bn_gamma, bn_beta, l);
        k_apply<<<(NN * 16 + 255) / 256, 256>>>();
    }

    /* ---- pooling ---- */
    k_pool_zero<<<(NB * HID + 255) / 256, 256>>>(out);
    k_pool_sum<<<WARP8, 256>>>(batch, out);
    k_pool_div<<<(NB * HID + 255) / 256, 256>>>(out);
}

// round 16
// speedup vs baseline: 1.0261x; 1.0261x over previous
#include <cuda_runtime.h>
#include <cuda_fp16.h>
#include <math.h>

#define NN   100000
#define EE   1600000
#define HID  64
#define NL   5
#define NB   512
#define SCAN_T 512
#define SCAN_BLOCKS 196          /* ceil(100000/512) */

/* ------------------------------------------------------------------ */
/* device scratch (h lives only as fp16)                               */
/* ------------------------------------------------------------------ */
__device__ __half g_h16[NN * HID];            /* node features (fp16) */
__device__ __half g_u[NN * HID];
__device__ float  g_t[NN * HID];
__device__ __half g_e[(size_t)EE * HID];      /* 204.8 MB, CSR order  */
__device__ __half g_wh[NL * 4 * HID * HID];   /* fp16 MLP weights     */
__device__ int    g_deg[NN];
__device__ int    g_cur[NN];
__device__ int    g_incl[SCAN_BLOCKS * SCAN_T];
__device__ int    g_bsum[SCAN_BLOCKS];
__device__ int    g_off[NN + 1];
__device__ int    g_csr_src[EE];
__device__ int    g_csr_eid[EE];
__device__ double g_colsum[HID];
__device__ double g_colsq[HID];
__device__ float  g_scale[HID];
__device__ float  g_shift[HID];
__device__ float  g_gcnt[NB];

/* ------------------------------------------------------------------ */
/* packed f32x2 helpers                                                */
/* ------------------------------------------------------------------ */
typedef unsigned long long pf2;

__device__ __forceinline__ pf2 pk2(float lo, float hi) {
    pf2 d;
    asm("mov.b64 %0, {%1, %2};" : "=l"(d)
        : "r"(__float_as_uint(lo)), "r"(__float_as_uint(hi)));
    return d;
}
__device__ __forceinline__ void upk2(pf2 d, float &lo, float &hi) {
    unsigned a, b;
    asm("mov.b64 {%0, %1}, %2;" : "=r"(a), "=r"(b) : "l"(d));
    lo = __uint_as_float(a); hi = __uint_as_float(b);
}
__device__ __forceinline__ pf2 fma2(pf2 a, pf2 b, pf2 c) {
    pf2 d;
    asm("fma.rn.f32x2 %0, %1, %2, %3;" : "=l"(d) : "l"(a), "l"(b), "l"(c));
    return d;
}
__device__ __forceinline__ unsigned sptr(const void *p) {
    return (unsigned)__cvta_generic_to_shared(p);
}
/* streaming (evict-first) half2 load via b32 */
__device__ __forceinline__ __half2 ldcs_h2(const __half *p) {
    unsigned u = __ldcs((const unsigned *)p);
    return *(__half2 *)&u;
}

/* ------------------------------------------------------------------ */
/* CSR build                                                           */
/* ------------------------------------------------------------------ */
__global__ void k_zero2() {
    int i = blockIdx.x * blockDim.x + threadIdx.x;
    if (i < NN) { g_deg[i] = 0; g_cur[i] = 0; }
    if (i < HID) { g_colsum[i] = 0.0; g_colsq[i] = 0.0; }
}

__global__ void k_hist(const int *__restrict__ ei) {
    int i = blockIdx.x * blockDim.x + threadIdx.x;
    if (i < EE) atomicAdd(&g_deg[__ldcs(ei + EE + i)], 1);
}

__global__ void k_scan_partial() {
    __shared__ int s[SCAN_T];
    int tid = threadIdx.x;
    int idx = blockIdx.x * SCAN_T + tid;
    int v = (idx < NN) ? g_deg[idx] : 0;
    s[tid] = v;
    __syncthreads();
#pragma unroll
    for (int d = 1; d < SCAN_T; d <<= 1) {
        int t = (tid >= d) ? s[tid - d] : 0;
        __syncthreads();
        s[tid] += t;
        __syncthreads();
    }
    g_incl[idx] = s[tid];
    if (tid == SCAN_T - 1) g_bsum[blockIdx.x] = s[tid];
}

__global__ void k_scan_bsum() {
    __shared__ int s[256];
    int tid = threadIdx.x;
    int v = (tid < SCAN_BLOCKS) ? g_bsum[tid] : 0;
    s[tid] = v;
    __syncthreads();
#pragma unroll
    for (int d = 1; d < 256; d <<= 1) {
        int t = (tid >= d) ? s[tid - d] : 0;
        __syncthreads();
        s[tid] += t;
        __syncthreads();
    }
    if (tid < SCAN_BLOCKS) g_bsum[tid] = s[tid] - v;   /* exclusive */
}

__global__ void k_scan_add() {
    int i = blockIdx.x * blockDim.x + threadIdx.x;
    if (i <= NN)
        g_off[i] = (i == 0) ? 0 : g_incl[i - 1] + g_bsum[(i - 1) >> 9];
}

__global__ void k_scatter(const int *__restrict__ ei) {
    int i = blockIdx.x * blockDim.x + threadIdx.x;
    if (i < EE) {
        int d = __ldcs(ei + EE + i);
        int p = g_off[d] + atomicAdd(&g_cur[d], 1);
        g_csr_src[p] = __ldcs(ei + i);
        g_csr_eid[p] = i;
    }
}

/* ------------------------------------------------------------------ */
/* MLP weight fp32 -> fp16                                             */
/* ------------------------------------------------------------------ */
__global__ void k_wconv(const float *__restrict__ W) {
    int i = blockIdx.x * blockDim.x + threadIdx.x;
    if (i < NL * 4 * HID * HID) g_wh[i] = __float2half(W[i]);
}

/* ------------------------------------------------------------------ */
/* edge projection (GEMM tile): e[slot] = edge_attr[eid]@W + b (fp16)  */
/* ------------------------------------------------------------------ */
__global__ void __launch_bounds__(256, 4)
k_edgeproj(const float *__restrict__ ea,
           const float *__restrict__ W,
           const float *__restrict__ b) {
    __shared__ float sA[128 * 16];
    __shared__ float sW[16 * 64];
    __shared__ float sB[64];
    int tid = threadIdx.x;
    int m0 = blockIdx.x * 128;

    ((float4 *)sW)[tid] = ((const float4 *)W)[tid];
    if (tid < 16) ((float4 *)sB)[tid] = ((const float4 *)b)[tid];

    for (int i = tid; i < 512; i += 256) {
        int r = i >> 2, q = i & 3;
        float4 v = make_float4(0.f, 0.f, 0.f, 0.f);
        int slot = m0 + r;
        if (slot < EE) {
            int eid = __ldcs(g_csr_eid + slot);
            v = __ldcs((const float4 *)(ea + (size_t)eid * 16 + q * 4));
        }
        *(float4 *)(sA + r * 16 + q * 4) = v;
    }
    __syncthreads();

    int tx = tid & 15, ty = tid >> 4;
    int r0 = ty * 8, c0 = tx * 4;

    pf2 acc[8][2];
#pragma unroll
    for (int i = 0; i < 8; i++) { acc[i][0] = 0ull; acc[i][1] = 0ull; }

#pragma unroll
    for (int k = 0; k < 16; k++) {
        float4 w = *(const float4 *)(sW + k * 64 + c0);
        pf2 w01 = pk2(w.x, w.y), w23 = pk2(w.z, w.w);
#pragma unroll
        for (int i = 0; i < 8; i++) {
            float av = sA[(r0 + i) * 16 + k];
            pf2 ad = pk2(av, av);
            acc[i][0] = fma2(ad, w01, acc[i][0]);
            acc[i][1] = fma2(ad, w23, acc[i][1]);
        }
    }

    float bx = sB[c0], by = sB[c0 + 1], bz = sB[c0 + 2], bw = sB[c0 + 3];
#pragma unroll
    for (int i = 0; i < 8; i++) {
        int slot = m0 + r0 + i;
        if (slot < EE) {
            float x0, x1, x2, x3;
            upk2(acc[i][0], x0, x1);
            upk2(acc[i][1], x2, x3);
            union { uint2 u2; __half2 h2[2]; } pk;
            pk.h2[0] = __floats2half2_rn(x0 + bx, x1 + by);
            pk.h2[1] = __floats2half2_rn(x2 + bz, x3 + bw);
            __stcs((uint2 *)(g_e + (size_t)slot * 64 + c0), pk.u2);
        }
    }
}

/* ------------------------------------------------------------------ */
/* node projection (fp32 FFMA2 tile, runs once); writes h16 only       */
/* ------------------------------------------------------------------ */
#define NP_SMEM ((128 * 64 + 64 * 64 + 64) * 4)

__global__ void __launch_bounds__(256, 2)
k_nodeproj(const float *__restrict__ in,
           const float *__restrict__ W, const float *__restrict__ b) {
    extern __shared__ float smf[];
    float *sA = smf;
    float *sW = sA + 128 * 64;
    float *sB = sW + 64 * 64;
    int tid = threadIdx.x;
    int m0 = blockIdx.x * 128;

    for (int i = tid; i < 2048; i += 256) {
        int r = i >> 4, q = i & 15;
        float4 v = make_float4(0.f, 0.f, 0.f, 0.f);
        if (m0 + r < NN)
            v = *(const float4 *)(in + (size_t)(m0 + r) * 64 + q * 4);
        *(float4 *)(sA + r * 64 + q * 4) = v;
    }
    for (int i = tid; i < 1024; i += 256)
        ((float4 *)sW)[i] = ((const float4 *)W)[i];
    if (tid < 16) ((float4 *)sB)[tid] = ((const float4 *)b)[tid];
    __syncthreads();

    int tx = tid & 15, ty = tid >> 4;
    int r0 = ty * 8, c0 = tx * 4;

    pf2 acc[8][2];
#pragma unroll
    for (int i = 0; i < 8; i++) { acc[i][0] = 0ull; acc[i][1] = 0ull; }

#pragma unroll
    for (int kk = 0; kk < 64; kk += 4) {
        float4 a[8];
#pragma unroll
        for (int i = 0; i < 8; i++)
            a[i] = *(const float4 *)(sA + (r0 + i) * 64 + kk);
#pragma unroll
        for (int k4 = 0; k4 < 4; k4++) {
            float4 w = *(const float4 *)(sW + (kk + k4) * 64 + c0);
            pf2 w01 = pk2(w.x, w.y), w23 = pk2(w.z, w.w);
#pragma unroll
            for (int i = 0; i < 8; i++) {
                float av = (k4 == 0) ? a[i].x : (k4 == 1) ? a[i].y
                         : (k4 == 2) ? a[i].z : a[i].w;
                pf2 ad = pk2(av, av);
                acc[i][0] = fma2(ad, w01, acc[i][0]);
                acc[i][1] = fma2(ad, w23, acc[i][1]);
            }
        }
    }

    float bx = sB[c0], by = sB[c0 + 1], bz = sB[c0 + 2], bw = sB[c0 + 3];
#pragma unroll
    for (int i = 0; i < 8; i++) {
        if (m0 + r0 + i < NN) {
            float x0, x1, x2, x3;
            upk2(acc[i][0], x0, x1);
            upk2(acc[i][1], x2, x3);
            x0 += bx; x1 += by; x2 += bz; x3 += bw;
            union { uint2 u2; __half2 h2[2]; } pk;
            pk.h2[0] = __floats2half2_rn(x0, x1);
            pk.h2[1] = __floats2half2_rn(x2, x3);
            *(uint2 *)(g_h16 + (size_t)(m0 + r0 + i) * 64 + c0) = pk.u2;
        }
    }
}

/* ------------------------------------------------------------------ */
/* aggregation: u[v] = (1+eps)*h16[v] + sum relu(h16[s]+e)             */
/* u written evict-first (single-use stream; protects h16 in L2)       */
/* ------------------------------------------------------------------ */
__global__ void k_aggr(const float *__restrict__ eps_arr, int l) {
    int v = blockIdx.x * 8 + (threadIdx.x >> 5);
    if (v >= NN) return;
    int lane = threadIdx.x & 31;
    int f0 = lane * 2;
    float ep = 1.0f + __ldg(&eps_arr[l]);

    float2 hv = __half22float2(*(const __half2 *)(g_h16 + (size_t)v * 64 + f0));
    float ax = ep * hv.x, ay = ep * hv.y;

    int beg = g_off[v], end = g_off[v + 1];
    const __half2 z2 = __float2half2_rn(0.f);
    int p = beg;
    for (; p + 2 <= end; p += 2) {
        int s0 = __ldcs(g_csr_src + p), s1 = __ldcs(g_csr_src + p + 1);
        __half2 h0 = *(const __half2 *)(g_h16 + (size_t)s0 * 64 + f0);
        __half2 h1 = *(const __half2 *)(g_h16 + (size_t)s1 * 64 + f0);
        __half2 e0 = ldcs_h2(g_e + (size_t)p * 64 + f0);
        __half2 e1 = ldcs_h2(g_e + (size_t)(p + 1) * 64 + f0);
        float2 m0 = __half22float2(__hmax2(__hadd2(h0, e0), z2));
        float2 m1 = __half22float2(__hmax2(__hadd2(h1, e1), z2));
        ax += m0.x + m1.x;
        ay += m0.y + m1.y;
    }
    if (p < end) {
        int s0 = __ldcs(g_csr_src + p);
        __half2 h0 = *(const __half2 *)(g_h16 + (size_t)s0 * 64 + f0);
        __half2 e0 = ldcs_h2(g_e + (size_t)p * 64 + f0);
        float2 m0 = __half22float2(__hmax2(__hadd2(h0, e0), z2));
        ax += m0.x;
        ay += m0.y;
    }
    union { unsigned u; __half2 h2; } o;
    o.h2 = __floats2half2_rn(ax, ay);
    __stcs((unsigned *)(g_u + (size_t)v * 64 + f0), o.u);
}

/* ------------------------------------------------------------------ */
/* MLP via HMMA: 4 x (64x64 linear [+relu]), fp16 in (streaming),      */
/* fp32 out (t, streaming)                                             */
/* ------------------------------------------------------------------ */
#define MLP_SMEM (128*72*2*2 + 64*72*2 + 64*4 + 64*4 + 64*4)

__global__ void __launch_bounds__(256, 3)
k_mlp_mma(const __half *__restrict__ in, float *__restrict__ out,
          const __half *__restrict__ Wh, const float *__restrict__ bb, int M) {
    extern __shared__ char smc[];
    __half *sA0  = (__half *)smc;          /* 128 x 72 */
    __half *sA1  = sA0 + 128 * 72;         /* 128 x 72 */
    __half *sW   = sA1 + 128 * 72;         /* 64 x 72  */
    float  *sBias = (float *)(sW + 64 * 72);
    float  *sPs  = sBias + 64;
    float  *sPq  = sPs + 64;

    int tid = threadIdx.x;
    int lane = tid & 31, wid = tid >> 5;
    int m0 = wid * 16;
    int mg0 = blockIdx.x * 128;

    if (tid < 64) { sPs[tid] = 0.f; sPq[tid] = 0.f; }

#pragma unroll
    for (int j = 0; j < 4; j++) {
        int idx = tid + 256 * j;
        int r = idx >> 3, q = idx & 7;
        uint4 v = make_uint4(0, 0, 0, 0);
        if (mg0 + r < M)
            v = __ldcs((const uint4 *)(in + (size_t)(mg0 + r) * 64 + q * 8));
        *(uint4 *)(sA0 + r * 72 + q * 8) = v;
    }

    int gid = lane >> 2, tig = lane & 3;

    for (int s = 0; s < 4; s++) {
        __syncthreads();
        const __half *Ws = Wh + s * 4096;
        {
            int idx = tid * 2;
            int r = idx >> 3, q = idx & 7;
            *(uint4 *)(sW + r * 72 + q * 8) = *(const uint4 *)(Ws + r * 64 + q * 8);
            idx++;
            r = idx >> 3; q = idx & 7;
            *(uint4 *)(sW + r * 72 + q * 8) = *(const uint4 *)(Ws + r * 64 + q * 8);
        }
        if (tid < 64) sBias[tid] = bb[s * 64 + tid];
        __syncthreads();

        __half *sIn  = (s & 1) ? sA1 : sA0;
        __half *sOut = (s & 1) ? sA0 : sA1;

        float acc[8][4];
#pragma unroll
        for (int nt = 0; nt < 8; nt++)
#pragma unroll
            for (int i = 0; i < 4; i++) acc[nt][i] = 0.f;

#pragma unroll
        for (int kc = 0; kc < 4; kc++) {
            int k = kc * 16;
            unsigned a0, a1, a2, a3;
            unsigned aaddr = sptr(sIn + (m0 + (lane & 15)) * 72 + k + ((lane >> 4) << 3));
            asm volatile("ldmatrix.sync.aligned.m8n8.x4.shared.b16 {%0,%1,%2,%3}, [%4];"
                         : "=r"(a0), "=r"(a1), "=r"(a2), "=r"(a3) : "r"(aaddr));
#pragma unroll
            for (int nt = 0; nt < 8; nt++) {
                unsigned b0, b1;
                unsigned baddr = sptr(sW + (k + (lane & 15)) * 72 + nt * 8);
                asm volatile("ldmatrix.sync.aligned.m8n8.x2.trans.shared.b16 {%0,%1}, [%2];"
                             : "=r"(b0), "=r"(b1) : "r"(baddr));
                asm volatile(
                    "mma.sync.aligned.m16n8k16.row.col.f32.f16.f16.f32 "
                    "{%0,%1,%2,%3}, {%4,%5,%6,%7}, {%8,%9}, {%0,%1,%2,%3};"
                    : "+f"(acc[nt][0]), "+f"(acc[nt][1]),
                      "+f"(acc[nt][2]), "+f"(acc[nt][3])
                    : "r"(a0), "r"(a1), "r"(a2), "r"(a3), "r"(b0), "r"(b1));
            }
        }

        bool last = (s == 3);
#pragma unroll
        for (int nt = 0; nt < 8; nt++) {
            int col = nt * 8 + 2 * tig;
            float b0f = sBias[col], b1f = sBias[col + 1];
            float v0 = acc[nt][0] + b0f;
            float v1 = acc[nt][1] + b1f;
            float v2 = acc[nt][2] + b0f;
            float v3 = acc[nt][3] + b1f;
            if (!last) {
                v0 = fmaxf(v0, 0.f); v1 = fmaxf(v1, 0.f);
                v2 = fmaxf(v2, 0.f); v3 = fmaxf(v3, 0.f);
                *(__half2 *)(sOut + (m0 + gid) * 72 + col)     = __floats2half2_rn(v0, v1);
                *(__half2 *)(sOut + (m0 + gid + 8) * 72 + col) = __floats2half2_rn(v2, v3);
            } else {
                int r0g = mg0 + m0 + gid, r1g = r0g + 8;
                bool ok0 = r0g < M, ok1 = r1g < M;
                if (ok0) __stcs((float2 *)(out + (size_t)r0g * 64 + col),
                                make_float2(v0, v1));
                if (ok1) __stcs((float2 *)(out + (size_t)r1g * 64 + col),
                                make_float2(v2, v3));
                if (!ok0) { v0 = 0.f; v1 = 0.f; }
                if (!ok1) { v2 = 0.f; v3 = 0.f; }
                float s0 = v0 + v2, s1 = v1 + v3;
                float q0 = v0 * v0 + v2 * v2, q1 = v1 * v1 + v3 * v3;
#pragma unroll
                for (int o = 4; o < 32; o <<= 1) {
                    s0 += __shfl_xor_sync(0xffffffffu, s0, o);
                    s1 += __shfl_xor_sync(0xffffffffu, s1, o);
                    q0 += __shfl_xor_sync(0xffffffffu, q0, o);
                    q1 += __shfl_xor_sync(0xffffffffu, q1, o);
                }
                if (lane < 4) {
                    atomicAdd(&sPs[col], s0);
                    atomicAdd(&sPs[col + 1], s1);
                    atomicAdd(&sPq[col], q0);
                    atomicAdd(&sPq[col + 1], q1);
                }
            }
        }
    }

    __syncthreads();
    if (tid < 64) {
        atomicAdd(&g_colsum[tid], (double)sPs[tid]);
        atomicAdd(&g_colsq[tid], (double)sPq[tid]);
    }
}

/* ------------------------------------------------------------------ */
/* BN finalize (single block; re-zeroes accumulators)                  */
/* ------------------------------------------------------------------ */
__global__ void k_bn_finalize(const float *__restrict__ gamma,
                              const float *__restrict__ beta, int l) {
    int c = threadIdx.x;
    if (c < HID) {
        double mu  = g_colsum[c] / (double)NN;
        double var = g_colsq[c] / (double)NN - mu * mu;
        float s = (float)(1.0 / sqrt(var + 1e-5)) * gamma[l * HID + c];
        g_scale[c] = s;
        g_shift[c] = beta[l * HID + c] - (float)mu * s;
        g_colsum[c] = 0.0;
        g_colsq[c]  = 0.0;
    }
}

/* ------------------------------------------------------------------ */
/* BN apply + relu + residual; t read evict-first                      */
/* ------------------------------------------------------------------ */
__global__ void k_apply() {
    __shared__ float ss[64], sh[64];
    int tid = threadIdx.x;
    if (tid < 64) { ss[tid] = g_scale[tid]; sh[tid] = g_shift[tid]; }
    __syncthreads();
    int i = blockIdx.x * blockDim.x + tid;
    if (i < NN * 16) {
        int c = (i & 15) * 4;
        float4 t = __ldcs(((const float4 *)g_t) + i);
        union { uint2 u2; __half2 h2[2]; } H;
        H.u2 = ((const uint2 *)g_h16)[i];
        float2 h01 = __half22float2(H.h2[0]);
        float2 h23 = __half22float2(H.h2[1]);
        float r0 = fmaxf(fmaf(t.x, ss[c + 0], sh[c + 0]), 0.f) + h01.x;
        float r1 = fmaxf(fmaf(t.y, ss[c + 1], sh[c + 1]), 0.f) + h01.y;
        float r2 = fmaxf(fmaf(t.z, ss[c + 2], sh[c + 2]), 0.f) + h23.x;
        float r3 = fmaxf(fmaf(t.w, ss[c + 3], sh[c + 3]), 0.f) + h23.y;
        union { uint2 u2; __half2 h2[2]; } pk;
        pk.h2[0] = __floats2half2_rn(r0, r1);
        pk.h2[1] = __floats2half2_rn(r2, r3);
        ((uint2 *)g_h16)[i] = pk.u2;
    }
}

/* ------------------------------------------------------------------ */
/* global mean pool (reads h16)                                        */
/* ------------------------------------------------------------------ */
__global__ void k_pool_zero(float *__restrict__ out) {
    int i = blockIdx.x * blockDim.x + threadIdx.x;
    if (i < NB * HID) out[i] = 0.f;
    if (i < NB) g_gcnt[i] = 0.f;
}

__global__ void k_pool_sum(const int *__restrict__ batch,
                           float *__restrict__ out) {
    int v = blockIdx.x * 8 + (threadIdx.x >> 5);
    if (v >= NN) return;
    int lane = threadIdx.x & 31;
    int f0 = lane * 2;
    int b = batch[v];
    float2 hv = __half22float2(*(const __half2 *)(g_h16 + (size_t)v * 64 + f0));
    atomicAdd(&out[b * 64 + f0], hv.x);
    atomicAdd(&out[b * 64 + f0 + 1], hv.y);
    if (lane == 0) atomicAdd(&g_gcnt[b], 1.0f);
}

__global__ void k_pool_div(float *__restrict__ out) {
    int i = blockIdx.x * blockDim.x + threadIdx.x;
    if (i < NB * HID) out[i] /= fmaxf(g_gcnt[i >> 6], 1.0f);
}

/* ------------------------------------------------------------------ */
/* launch                                                              */
/* ------------------------------------------------------------------ */
extern "C" void kernel_launch(void *const *d_in, const int *in_sizes, int n_in,
                              void *d_out, int out_size) {
    const float *x         = (const float *)d_in[0];
    const float *edge_attr = (const float *)d_in[1];
    const float *node_W    = (const float *)d_in[2];
    const float *node_b    = (const float *)d_in[3];
    const float *edge_W    = (const float *)d_in[4];
    const float *edge_b    = (const float *)d_in[5];
    const float *eps_arr   = (const float *)d_in[6];
    const float *mlp_W     = (const float *)d_in[7];
    const float *mlp_b     = (const float *)d_in[8];
    const float *bn_gamma  = (const float *)d_in[9];
    const float *bn_beta   = (const float *)d_in[10];
    const int   *edge_index = (const int *)d_in[11];
    const int   *batch      = (const int *)d_in[12];
    float *out = (float *)d_out;

    cudaFuncSetAttribute(k_nodeproj,
                         cudaFuncAttributeMaxDynamicSharedMemorySize, NP_SMEM);
    cudaFuncSetAttribute(k_mlp_mma,
                         cudaFuncAttributeMaxDynamicSharedMemorySize, MLP_SMEM);

    float *pt;
    __half *pu, *pwh;
    cudaGetSymbolAddress((void **)&pt, g_t);
    cudaGetSymbolAddress((void **)&pu, g_u);
    cudaGetSymbolAddress((void **)&pwh, g_wh);

    const int LIN_BLOCKS = (NN + 127) / 128;       /* 782   */
    const int EP_BLOCKS  = (EE + 127) / 128;       /* 12500 */
    const int WARP8      = (NN + 7) / 8;           /* 12500 */

    /* ---- preprocessing ---- */
    k_zero2<<<(NN + 255) / 256, 256>>>();
    k_hist<<<(EE + 255) / 256, 256>>>(edge_index);
    k_scan_partial<<<SCAN_BLOCKS, SCAN_T>>>();
    k_scan_bsum<<<1, 256>>>();
    k_scan_add<<<(NN + 256) / 256, 256>>>();
    k_scatter<<<(EE + 255) / 256, 256>>>(edge_index);
    k_edgeproj<<<EP_BLOCKS, 256>>>(edge_attr, edge_W, edge_b);
    k_wconv<<<(NL * 4 * HID * HID + 255) / 256, 256>>>(mlp_W);

    /* node projection */
    k_nodeproj<<<LIN_BLOCKS, 256, NP_SMEM>>>(x, node_W, node_b);

    /* ---- layers ---- */
    for (int l = 0; l < NL; l++) {
        k_aggr<<<WARP8, 256>>>(eps_arr, l);
        k_mlp_mma<<<LIN_BLOCKS, 256, MLP_SMEM>>>(
            pu, pt, pwh + (size_t)l * 4 * 4096, mlp_b + (size_t)l * 4 * 64, NN);
        k_bn_finalize<<<1, 64>>>(bn_gamma, bn_beta, l);
        k_apply<<<(NN * 16 + 255) / 256, 256>>>();
    }

    /* ---- pooling ---- */
    k_pool_zero<<<(NB * HID + 255) / 256, 256>>>(out);
    k_pool_sum<<<WARP8, 256>>>(batch, out);
    k_pool_div<<<(NB * HID + 255) / 256, 256>>>(out);
}

// round 17
// speedup vs baseline: 1.0389x; 1.0125x over previous
#include <cuda_runtime.h>
#include <cuda_fp16.h>
#include <math.h>

#define NN   100000
#define EE   1600000
#define HID  64
#define NL   5
#define NB   512
#define SCAN_T 512
#define SCAN_BLOCKS 196          /* ceil(100000/512) */

/* ------------------------------------------------------------------ */
/* device scratch (h lives only as fp16)                               */
/* ------------------------------------------------------------------ */
__device__ __half g_h16[NN * HID];            /* node features (fp16) */
__device__ __half g_u[NN * HID];
__device__ float  g_t[NN * HID];
__device__ __half g_e[(size_t)EE * HID];      /* 204.8 MB, CSR order  */
__device__ __half g_wh[NL * 4 * HID * HID];   /* fp16 MLP weights     */
__device__ int    g_deg[NN];
__device__ int    g_cur[NN];
__device__ int    g_incl[SCAN_BLOCKS * SCAN_T];
__device__ int    g_bsum[SCAN_BLOCKS];
__device__ int    g_off[NN + 1];
__device__ int    g_csr_src[EE];
__device__ int    g_csr_eid[EE];
__device__ double g_colsum[HID];
__device__ double g_colsq[HID];
__device__ float  g_gcnt[NB];

/* ------------------------------------------------------------------ */
/* packed f32x2 helpers                                                */
/* ------------------------------------------------------------------ */
typedef unsigned long long pf2;

__device__ __forceinline__ pf2 pk2(float lo, float hi) {
    pf2 d;
    asm("mov.b64 %0, {%1, %2};" : "=l"(d)
        : "r"(__float_as_uint(lo)), "r"(__float_as_uint(hi)));
    return d;
}
__device__ __forceinline__ void upk2(pf2 d, float &lo, float &hi) {
    unsigned a, b;
    asm("mov.b64 {%0, %1}, %2;" : "=r"(a), "=r"(b) : "l"(d));
    lo = __uint_as_float(a); hi = __uint_as_float(b);
}
__device__ __forceinline__ pf2 fma2(pf2 a, pf2 b, pf2 c) {
    pf2 d;
    asm("fma.rn.f32x2 %0, %1, %2, %3;" : "=l"(d) : "l"(a), "l"(b), "l"(c));
    return d;
}
__device__ __forceinline__ unsigned sptr(const void *p) {
    return (unsigned)__cvta_generic_to_shared(p);
}
/* streaming (evict-first) half2 load via b32 */
__device__ __forceinline__ __half2 ldcs_h2(const __half *p) {
    unsigned u = __ldcs((const unsigned *)p);
    return *(__half2 *)&u;
}

/* ------------------------------------------------------------------ */
/* CSR build                                                           */
/* ------------------------------------------------------------------ */
__global__ void k_zero2() {
    int i = blockIdx.x * blockDim.x + threadIdx.x;
    if (i < NN) { g_deg[i] = 0; g_cur[i] = 0; }
    if (i < HID) { g_colsum[i] = 0.0; g_colsq[i] = 0.0; }
}

__global__ void k_hist(const int *__restrict__ ei) {
    int i = blockIdx.x * blockDim.x + threadIdx.x;
    if (i < EE) atomicAdd(&g_deg[__ldcs(ei + EE + i)], 1);
}

__global__ void k_scan_partial() {
    __shared__ int s[SCAN_T];
    int tid = threadIdx.x;
    int idx = blockIdx.x * SCAN_T + tid;
    int v = (idx < NN) ? g_deg[idx] : 0;
    s[tid] = v;
    __syncthreads();
#pragma unroll
    for (int d = 1; d < SCAN_T; d <<= 1) {
        int t = (tid >= d) ? s[tid - d] : 0;
        __syncthreads();
        s[tid] += t;
        __syncthreads();
    }
    g_incl[idx] = s[tid];
    if (tid == SCAN_T - 1) g_bsum[blockIdx.x] = s[tid];
}

__global__ void k_scan_bsum() {
    __shared__ int s[256];
    int tid = threadIdx.x;
    int v = (tid < SCAN_BLOCKS) ? g_bsum[tid] : 0;
    s[tid] = v;
    __syncthreads();
#pragma unroll
    for (int d = 1; d < 256; d <<= 1) {
        int t = (tid >= d) ? s[tid - d] : 0;
        __syncthreads();
        s[tid] += t;
        __syncthreads();
    }
    if (tid < SCAN_BLOCKS) g_bsum[tid] = s[tid] - v;   /* exclusive */
}

__global__ void k_scan_add() {
    int i = blockIdx.x * blockDim.x + threadIdx.x;
    if (i <= NN)
        g_off[i] = (i == 0) ? 0 : g_incl[i - 1] + g_bsum[(i - 1) >> 9];
}

__global__ void k_scatter(const int *__restrict__ ei) {
    int i = blockIdx.x * blockDim.x + threadIdx.x;
    if (i < EE) {
        int d = __ldcs(ei + EE + i);
        int p = g_off[d] + atomicAdd(&g_cur[d], 1);
        g_csr_src[p] = __ldcs(ei + i);
        g_csr_eid[p] = i;
    }
}

/* ------------------------------------------------------------------ */
/* MLP weight fp32 -> fp16                                             */
/* ------------------------------------------------------------------ */
__global__ void k_wconv(const float *__restrict__ W) {
    int i = blockIdx.x * blockDim.x + threadIdx.x;
    if (i < NL * 4 * HID * HID) g_wh[i] = __float2half(W[i]);
}

/* ------------------------------------------------------------------ */
/* edge projection (GEMM tile): e[slot] = edge_attr[eid]@W + b (fp16)  */
/* ------------------------------------------------------------------ */
__global__ void __launch_bounds__(256, 4)
k_edgeproj(const float *__restrict__ ea,
           const float *__restrict__ W,
           const float *__restrict__ b) {
    __shared__ float sA[128 * 16];
    __shared__ float sW[16 * 64];
    __shared__ float sB[64];
    int tid = threadIdx.x;
    int m0 = blockIdx.x * 128;

    ((float4 *)sW)[tid] = ((const float4 *)W)[tid];
    if (tid < 16) ((float4 *)sB)[tid] = ((const float4 *)b)[tid];

    for (int i = tid; i < 512; i += 256) {
        int r = i >> 2, q = i & 3;
        float4 v = make_float4(0.f, 0.f, 0.f, 0.f);
        int slot = m0 + r;
        if (slot < EE) {
            int eid = __ldcs(g_csr_eid + slot);
            v = __ldcs((const float4 *)(ea + (size_t)eid * 16 + q * 4));
        }
        *(float4 *)(sA + r * 16 + q * 4) = v;
    }
    __syncthreads();

    int tx = tid & 15, ty = tid >> 4;
    int r0 = ty * 8, c0 = tx * 4;

    pf2 acc[8][2];
#pragma unroll
    for (int i = 0; i < 8; i++) { acc[i][0] = 0ull; acc[i][1] = 0ull; }

#pragma unroll
    for (int k = 0; k < 16; k++) {
        float4 w = *(const float4 *)(sW + k * 64 + c0);
        pf2 w01 = pk2(w.x, w.y), w23 = pk2(w.z, w.w);
#pragma unroll
        for (int i = 0; i < 8; i++) {
            float av = sA[(r0 + i) * 16 + k];
            pf2 ad = pk2(av, av);
            acc[i][0] = fma2(ad, w01, acc[i][0]);
            acc[i][1] = fma2(ad, w23, acc[i][1]);
        }
    }

    float bx = sB[c0], by = sB[c0 + 1], bz = sB[c0 + 2], bw = sB[c0 + 3];
#pragma unroll
    for (int i = 0; i < 8; i++) {
        int slot = m0 + r0 + i;
        if (slot < EE) {
            float x0, x1, x2, x3;
            upk2(acc[i][0], x0, x1);
            upk2(acc[i][1], x2, x3);
            union { uint2 u2; __half2 h2[2]; } pk;
            pk.h2[0] = __floats2half2_rn(x0 + bx, x1 + by);
            pk.h2[1] = __floats2half2_rn(x2 + bz, x3 + bw);
            __stcs((uint2 *)(g_e + (size_t)slot * 64 + c0), pk.u2);
        }
    }
}

/* ------------------------------------------------------------------ */
/* node projection (fp32 FFMA2 tile, runs once); writes h16 only       */
/* ------------------------------------------------------------------ */
#define NP_SMEM ((128 * 64 + 64 * 64 + 64) * 4)

__global__ void __launch_bounds__(256, 2)
k_nodeproj(const float *__restrict__ in,
           const float *__restrict__ W, const float *__restrict__ b) {
    extern __shared__ float smf[];
    float *sA = smf;
    float *sW = sA + 128 * 64;
    float *sB = sW + 64 * 64;
    int tid = threadIdx.x;
    int m0 = blockIdx.x * 128;

    for (int i = tid; i < 2048; i += 256) {
        int r = i >> 4, q = i & 15;
        float4 v = make_float4(0.f, 0.f, 0.f, 0.f);
        if (m0 + r < NN)
            v = *(const float4 *)(in + (size_t)(m0 + r) * 64 + q * 4);
        *(float4 *)(sA + r * 64 + q * 4) = v;
    }
    for (int i = tid; i < 1024; i += 256)
        ((float4 *)sW)[i] = ((const float4 *)W)[i];
    if (tid < 16) ((float4 *)sB)[tid] = ((const float4 *)b)[tid];
    __syncthreads();

    int tx = tid & 15, ty = tid >> 4;
    int r0 = ty * 8, c0 = tx * 4;

    pf2 acc[8][2];
#pragma unroll
    for (int i = 0; i < 8; i++) { acc[i][0] = 0ull; acc[i][1] = 0ull; }

#pragma unroll
    for (int kk = 0; kk < 64; kk += 4) {
        float4 a[8];
#pragma unroll
        for (int i = 0; i < 8; i++)
            a[i] = *(const float4 *)(sA + (r0 + i) * 64 + kk);
#pragma unroll
        for (int k4 = 0; k4 < 4; k4++) {
            float4 w = *(const float4 *)(sW + (kk + k4) * 64 + c0);
            pf2 w01 = pk2(w.x, w.y), w23 = pk2(w.z, w.w);
#pragma unroll
            for (int i = 0; i < 8; i++) {
                float av = (k4 == 0) ? a[i].x : (k4 == 1) ? a[i].y
                         : (k4 == 2) ? a[i].z : a[i].w;
                pf2 ad = pk2(av, av);
                acc[i][0] = fma2(ad, w01, acc[i][0]);
                acc[i][1] = fma2(ad, w23, acc[i][1]);
            }
        }
    }

    float bx = sB[c0], by = sB[c0 + 1], bz = sB[c0 + 2], bw = sB[c0 + 3];
#pragma unroll
    for (int i = 0; i < 8; i++) {
        if (m0 + r0 + i < NN) {
            float x0, x1, x2, x3;
            upk2(acc[i][0], x0, x1);
            upk2(acc[i][1], x2, x3);
            x0 += bx; x1 += by; x2 += bz; x3 += bw;
            union { uint2 u2; __half2 h2[2]; } pk;
            pk.h2[0] = __floats2half2_rn(x0, x1);
            pk.h2[1] = __floats2half2_rn(x2, x3);
            *(uint2 *)(g_h16 + (size_t)(m0 + r0 + i) * 64 + c0) = pk.u2;
        }
    }
}

/* ------------------------------------------------------------------ */
/* aggregation: u[v] = (1+eps)*h16[v] + sum relu(h16[s]+e)             */
/* block 0 zeroes the BN accumulators for the upcoming MLP             */
/* ------------------------------------------------------------------ */
__global__ void k_aggr(const float *__restrict__ eps_arr, int l) {
    int tid = threadIdx.x;
    if (blockIdx.x == 0) {
        if (tid < 64)            g_colsum[tid]      = 0.0;
        else if (tid < 128)      g_colsq[tid - 64]  = 0.0;
    }
    int v = blockIdx.x * 8 + (tid >> 5);
    if (v >= NN) return;
    int lane = tid & 31;
    int f0 = lane * 2;
    float ep = 1.0f + __ldg(&eps_arr[l]);

    float2 hv = __half22float2(*(const __half2 *)(g_h16 + (size_t)v * 64 + f0));
    float ax = ep * hv.x, ay = ep * hv.y;

    int beg = g_off[v], end = g_off[v + 1];
    const __half2 z2 = __float2half2_rn(0.f);
    int p = beg;
    for (; p + 2 <= end; p += 2) {
        int s0 = __ldcs(g_csr_src + p), s1 = __ldcs(g_csr_src + p + 1);
        __half2 h0 = *(const __half2 *)(g_h16 + (size_t)s0 * 64 + f0);
        __half2 h1 = *(const __half2 *)(g_h16 + (size_t)s1 * 64 + f0);
        __half2 e0 = ldcs_h2(g_e + (size_t)p * 64 + f0);
        __half2 e1 = ldcs_h2(g_e + (size_t)(p + 1) * 64 + f0);
        float2 m0 = __half22float2(__hmax2(__hadd2(h0, e0), z2));
        float2 m1 = __half22float2(__hmax2(__hadd2(h1, e1), z2));
        ax += m0.x + m1.x;
        ay += m0.y + m1.y;
    }
    if (p < end) {
        int s0 = __ldcs(g_csr_src + p);
        __half2 h0 = *(const __half2 *)(g_h16 + (size_t)s0 * 64 + f0);
        __half2 e0 = ldcs_h2(g_e + (size_t)p * 64 + f0);
        float2 m0 = __half22float2(__hmax2(__hadd2(h0, e0), z2));
        ax += m0.x;
        ay += m0.y;
    }
    union { unsigned u; __half2 h2; } o;
    o.h2 = __floats2half2_rn(ax, ay);
    __stcs((unsigned *)(g_u + (size_t)v * 64 + f0), o.u);
}

/* ------------------------------------------------------------------ */
/* MLP via HMMA: 4 x (64x64 linear [+relu]), fp16 in (streaming),      */
/* fp32 out (t, streaming)                                             */
/* ------------------------------------------------------------------ */
#define MLP_SMEM (128*72*2*2 + 64*72*2 + 64*4 + 64*4 + 64*4)

__global__ void __launch_bounds__(256, 3)
k_mlp_mma(const __half *__restrict__ in, float *__restrict__ out,
          const __half *__restrict__ Wh, const float *__restrict__ bb, int M) {
    extern __shared__ char smc[];
    __half *sA0  = (__half *)smc;          /* 128 x 72 */
    __half *sA1  = sA0 + 128 * 72;         /* 128 x 72 */
    __half *sW   = sA1 + 128 * 72;         /* 64 x 72  */
    float  *sBias = (float *)(sW + 64 * 72);
    float  *sPs  = sBias + 64;
    float  *sPq  = sPs + 64;

    int tid = threadIdx.x;
    int lane = tid & 31, wid = tid >> 5;
    int m0 = wid * 16;
    int mg0 = blockIdx.x * 128;

    if (tid < 64) { sPs[tid] = 0.f; sPq[tid] = 0.f; }

#pragma unroll
    for (int j = 0; j < 4; j++) {
        int idx = tid + 256 * j;
        int r = idx >> 3, q = idx & 7;
        uint4 v = make_uint4(0, 0, 0, 0);
        if (mg0 + r < M)
            v = __ldcs((const uint4 *)(in + (size_t)(mg0 + r) * 64 + q * 8));
        *(uint4 *)(sA0 + r * 72 + q * 8) = v;
    }

    int gid = lane >> 2, tig = lane & 3;

    for (int s = 0; s < 4; s++) {
        __syncthreads();
        const __half *Ws = Wh + s * 4096;
        {
            int idx = tid * 2;
            int r = idx >> 3, q = idx & 7;
            *(uint4 *)(sW + r * 72 + q * 8) = *(const uint4 *)(Ws + r * 64 + q * 8);
            idx++;
            r = idx >> 3; q = idx & 7;
            *(uint4 *)(sW + r * 72 + q * 8) = *(const uint4 *)(Ws + r * 64 + q * 8);
        }
        if (tid < 64) sBias[tid] = bb[s * 64 + tid];
        __syncthreads();

        __half *sIn  = (s & 1) ? sA1 : sA0;
        __half *sOut = (s & 1) ? sA0 : sA1;

        float acc[8][4];
#pragma unroll
        for (int nt = 0; nt < 8; nt++)
#pragma unroll
            for (int i = 0; i < 4; i++) acc[nt][i] = 0.f;

#pragma unroll
        for (int kc = 0; kc < 4; kc++) {
            int k = kc * 16;
            unsigned a0, a1, a2, a3;
            unsigned aaddr = sptr(sIn + (m0 + (lane & 15)) * 72 + k + ((lane >> 4) << 3));
            asm volatile("ldmatrix.sync.aligned.m8n8.x4.shared.b16 {%0,%1,%2,%3}, [%4];"
                         : "=r"(a0), "=r"(a1), "=r"(a2), "=r"(a3) : "r"(aaddr));
#pragma unroll
            for (int nt = 0; nt < 8; nt++) {
                unsigned b0, b1;
                unsigned baddr = sptr(sW + (k + (lane & 15)) * 72 + nt * 8);
                asm volatile("ldmatrix.sync.aligned.m8n8.x2.trans.shared.b16 {%0,%1}, [%2];"
                             : "=r"(b0), "=r"(b1) : "r"(baddr));
                asm volatile(
                    "mma.sync.aligned.m16n8k16.row.col.f32.f16.f16.f32 "
                    "{%0,%1,%2,%3}, {%4,%5,%6,%7}, {%8,%9}, {%0,%1,%2,%3};"
                    : "+f"(acc[nt][0]), "+f"(acc[nt][1]),
                      "+f"(acc[nt][2]), "+f"(acc[nt][3])
                    : "r"(a0), "r"(a1), "r"(a2), "r"(a3), "r"(b0), "r"(b1));
            }
        }

        bool last = (s == 3);
#pragma unroll
        for (int nt = 0; nt < 8; nt++) {
            int col = nt * 8 + 2 * tig;
            float b0f = sBias[col], b1f = sBias[col + 1];
            float v0 = acc[nt][0] + b0f;
            float v1 = acc[nt][1] + b1f;
            float v2 = acc[nt][2] + b0f;
            float v3 = acc[nt][3] + b1f;
            if (!last) {
                v0 = fmaxf(v0, 0.f); v1 = fmaxf(v1, 0.f);
                v2 = fmaxf(v2, 0.f); v3 = fmaxf(v3, 0.f);
                *(__half2 *)(sOut + (m0 + gid) * 72 + col)     = __floats2half2_rn(v0, v1);
                *(__half2 *)(sOut + (m0 + gid + 8) * 72 + col) = __floats2half2_rn(v2, v3);
            } else {
                int r0g = mg0 + m0 + gid, r1g = r0g + 8;
                bool ok0 = r0g < M, ok1 = r1g < M;
                if (ok0) __stcs((float2 *)(out + (size_t)r0g * 64 + col),
                                make_float2(v0, v1));
                if (ok1) __stcs((float2 *)(out + (size_t)r1g * 64 + col),
                                make_float2(v2, v3));
                if (!ok0) { v0 = 0.f; v1 = 0.f; }
                if (!ok1) { v2 = 0.f; v3 = 0.f; }
                float s0 = v0 + v2, s1 = v1 + v3;
                float q0 = v0 * v0 + v2 * v2, q1 = v1 * v1 + v3 * v3;
#pragma unroll
                for (int o = 4; o < 32; o <<= 1) {
                    s0 += __shfl_xor_sync(0xffffffffu, s0, o);
                    s1 += __shfl_xor_sync(0xffffffffu, s1, o);
                    q0 += __shfl_xor_sync(0xffffffffu, q0, o);
                    q1 += __shfl_xor_sync(0xffffffffu, q1, o);
                }
                if (lane < 4) {
                    atomicAdd(&sPs[col], s0);
                    atomicAdd(&sPs[col + 1], s1);
                    atomicAdd(&sPq[col], q0);
                    atomicAdd(&sPq[col + 1], q1);
                }
            }
        }
    }

    __syncthreads();
    if (tid < 64) {
        atomicAdd(&g_colsum[tid], (double)sPs[tid]);
        atomicAdd(&g_colsq[tid], (double)sPq[tid]);
    }
}

/* ------------------------------------------------------------------ */
/* BN finalize (fp32, block-redundant) + apply + relu + residual       */
/* ------------------------------------------------------------------ */
__global__ void k_apply(const float *__restrict__ gamma,
                        const float *__restrict__ beta, int l) {
    __shared__ float ss[64], sh[64];
    int tid = threadIdx.x;
    if (tid < 64) {
        float cs = (float)g_colsum[tid];
        float cq = (float)g_colsq[tid];
        float mu  = cs * (1.0f / (float)NN);
        float var = cq * (1.0f / (float)NN) - mu * mu;
        float s = rsqrtf(var + 1e-5f) * __ldg(&gamma[l * HID + tid]);
        ss[tid] = s;
        sh[tid] = __ldg(&beta[l * HID + tid]) - mu * s;
    }
    __syncthreads();
    int i = blockIdx.x * blockDim.x + tid;
    if (i < NN * 16) {
        int c = (i & 15) * 4;
        float4 t = __ldcs(((const float4 *)g_t) + i);
        union { uint2 u2; __half2 h2[2]; } H;
        H.u2 = ((const uint2 *)g_h16)[i];
        float2 h01 = __half22float2(H.h2[0]);
        float2 h23 = __half22float2(H.h2[1]);
        float r0 = fmaxf(fmaf(t.x, ss[c + 0], sh[c + 0]), 0.f) + h01.x;
        float r1 = fmaxf(fmaf(t.y, ss[c + 1], sh[c + 1]), 0.f) + h01.y;
        float r2 = fmaxf(fmaf(t.z, ss[c + 2], sh[c + 2]), 0.f) + h23.x;
        float r3 = fmaxf(fmaf(t.w, ss[c + 3], sh[c + 3]), 0.f) + h23.y;
        union { uint2 u2; __half2 h2[2]; } pk;
        pk.h2[0] = __floats2half2_rn(r0, r1);
        pk.h2[1] = __floats2half2_rn(r2, r3);
        ((uint2 *)g_h16)[i] = pk.u2;
    }
}

/* ------------------------------------------------------------------ */
/* global mean pool (reads h16)                                        */
/* ------------------------------------------------------------------ */
__global__ void k_pool_zero(float *__restrict__ out) {
    int i = blockIdx.x * blockDim.x + threadIdx.x;
    if (i < NB * HID) out[i] = 0.f;
    if (i < NB) g_gcnt[i] = 0.f;
}

__global__ void k_pool_sum(const int *__restrict__ batch,
                           float *__restrict__ out) {
    int v = blockIdx.x * 8 + (threadIdx.x >> 5);
    if (v >= NN) return;
    int lane = threadIdx.x & 31;
    int f0 = lane * 2;
    int b = batch[v];
    float2 hv = __half22float2(*(const __half2 *)(g_h16 + (size_t)v * 64 + f0));
    atomicAdd(&out[b * 64 + f0], hv.x);
    atomicAdd(&out[b * 64 + f0 + 1], hv.y);
    if (lane == 0) atomicAdd(&g_gcnt[b], 1.0f);
}

__global__ void k_pool_div(float *__restrict__ out) {
    int i = blockIdx.x * blockDim.x + threadIdx.x;
    if (i < NB * HID) out[i] /= fmaxf(g_gcnt[i >> 6], 1.0f);
}

/* ------------------------------------------------------------------ */
/* launch                                                              */
/* ------------------------------------------------------------------ */
extern "C" void kernel_launch(void *const *d_in, const int *in_sizes, int n_in,
                              void *d_out, int out_size) {
    const float *x         = (const float *)d_in[0];
    const float *edge_attr = (const float *)d_in[1];
    const float *node_W    = (const float *)d_in[2];
    const float *node_b    = (const float *)d_in[3];
    const float *edge_W    = (const float *)d_in[4];
    const float *edge_b    = (const float *)d_in[5];
    const float *eps_arr   = (const float *)d_in[6];
    const float *mlp_W     = (const float *)d_in[7];
    const float *mlp_b     = (const float *)d_in[8];
    const float *bn_gamma  = (const float *)d_in[9];
    const float *bn_beta   = (const float *)d_in[10];
    const int   *edge_index = (const int *)d_in[11];
    const int   *batch      = (const int *)d_in[12];
    float *out = (float *)d_out;

    cudaFuncSetAttribute(k_nodeproj,
                         cudaFuncAttributeMaxDynamicSharedMemorySize, NP_SMEM);
    cudaFuncSetAttribute(k_mlp_mma,
                         cudaFuncAttributeMaxDynamicSharedMemorySize, MLP_SMEM);

    float *pt;
    __half *pu, *pwh;
    cudaGetSymbolAddress((void **)&pt, g_t);
    cudaGetSymbolAddress((void **)&pu, g_u);
    cudaGetSymbolAddress((void **)&pwh, g_wh);

    const int LIN_BLOCKS = (NN + 127) / 128;       /* 782   */
    const int EP_BLOCKS  = (EE + 127) / 128;       /* 12500 */
    const int WARP8      = (NN + 7) / 8;           /* 12500 */

    /* ---- preprocessing ---- */
    k_zero2<<<(NN + 255) / 256, 256>>>();
    k_hist<<<(EE + 255) / 256, 256>>>(edge_index);
    k_scan_partial<<<SCAN_BLOCKS, SCAN_T>>>();
    k_scan_bsum<<<1, 256>>>();
    k_scan_add<<<(NN + 256) / 256, 256>>>();
    k_scatter<<<(EE + 255) / 256, 256>>>(edge_index);
    k_edgeproj<<<EP_BLOCKS, 256>>>(edge_attr, edge_W, edge_b);
    k_wconv<<<(NL * 4 * HID * HID + 255) / 256, 256>>>(mlp_W);

    /* node projection */
    k_nodeproj<<<LIN_BLOCKS, 256, NP_SMEM>>>(x, node_W, node_b);

    /* ---- layers ---- */
    for (int l = 0; l < NL; l++) {
        k_aggr<<<WARP8, 256>>>(eps_arr, l);
        k_mlp_mma<<<LIN_BLOCKS, 256, MLP_SMEM>>>(
            pu, pt, pwh + (size_t)l * 4 * 4096, mlp_b + (size_t)l * 4 * 64, NN);
        k_apply<<<(NN * 16 + 255) / 256, 256>>>(bn_gamma, bn_beta, l);
    }

    /* ---- pooling ---- */
    k_pool_zero<<<(NB * HID + 255) / 256, 256>>>(out);
    k_pool_sum<<<WARP8, 256>>>(batch, out);
    k_pool_div<<<(NB * HID + 255) / 256, 256>>>(out);
}